// round 12
// baseline (speedup 1.0000x reference)
#include <cuda_runtime.h>
#include <math.h>
#include <stdint.h>

// Problem constants
#define BB   2
#define SS   2048
#define DDIM 1024
#define HH   16
#define HDD  64
#define MM   (BB*SS)   // 4096

// log2(e)/sqrt(HD): folded into Wq (via prep) and bq (epilogue)
#define QSCALE 0.18033688f

// Scratch:
//  g_qkv: Q,K in [b][h][s][hd]; V transposed [b][h][hd][s]  (tf32-rounded)
//  g_xr : tf32-rounded copies of the raw q/k/v activations [m][d]
//  g_wt : transposed + rounded weights Wt[n][k] (Wq pre-scaled by QSCALE)
__device__ float g_qkv[3][(size_t)BB * HH * SS * HDD];
__device__ float g_xr [3][(size_t)MM * DDIM];
__device__ float g_wt [3][(size_t)DDIM * DDIM];

// ---------------------------------------------------------------------------
// helpers
// ---------------------------------------------------------------------------
__device__ __forceinline__ float to_tf32(float x) {
    uint32_t u;
    asm("cvt.rna.tf32.f32 %0, %1;" : "=r"(u) : "f"(x));
    return __uint_as_float(u);
}

__device__ __forceinline__ float ex2f(float x) {
    float y;
    asm("ex2.approx.ftz.f32 %0, %1;" : "=f"(y) : "f"(x));
    return y;
}

__device__ __forceinline__ void mma_tf32(float c[4],
                                         uint32_t a0, uint32_t a1, uint32_t a2, uint32_t a3,
                                         uint32_t b0, uint32_t b1) {
    asm volatile(
        "mma.sync.aligned.m16n8k8.row.col.f32.tf32.tf32.f32 "
        "{%0,%1,%2,%3}, {%4,%5,%6,%7}, {%8,%9}, {%0,%1,%2,%3};"
        : "+f"(c[0]), "+f"(c[1]), "+f"(c[2]), "+f"(c[3])
        : "r"(a0), "r"(a1), "r"(a2), "r"(a3), "r"(b0), "r"(b1));
}

__device__ __forceinline__ uint32_t ldsf(const float* p) {
    return __float_as_uint(*p);
}

__device__ __forceinline__ void ldsm4(uint32_t& r0, uint32_t& r1,
                                      uint32_t& r2, uint32_t& r3, uint32_t addr) {
    asm volatile("ldmatrix.sync.aligned.m8n8.x4.shared.b16 {%0,%1,%2,%3}, [%4];"
                 : "=r"(r0), "=r"(r1), "=r"(r2), "=r"(r3) : "r"(addr));
}

__device__ __forceinline__ void cp16(uint32_t smem_dst, const void* gsrc) {
    asm volatile("cp.async.cg.shared.global [%0], [%1], 16;\n"
                 :: "r"(smem_dst), "l"(gsrc) : "memory");
}

// ---------------------------------------------------------------------------
// Pre-pass A: tf32-round the activations (elementwise).
// grid (4096, 3) x 256 threads, float4 per thread.
// ---------------------------------------------------------------------------
__global__ __launch_bounds__(256) void prep_x_kernel(
    const float* __restrict__ q, const float* __restrict__ k, const float* __restrict__ v)
{
    const int z = blockIdx.y;
    const float* src = (z == 0) ? q : (z == 1) ? k : v;
    float* dst = g_xr[z];
    const size_t i = ((size_t)blockIdx.x * 256 + threadIdx.x) * 4;
    float4 val = *reinterpret_cast<const float4*>(src + i);
    float4 o;
    o.x = to_tf32(val.x); o.y = to_tf32(val.y);
    o.z = to_tf32(val.z); o.w = to_tf32(val.w);
    *reinterpret_cast<float4*>(dst + i) = o;
}

// ---------------------------------------------------------------------------
// Pre-pass B: transpose + round weights:  Wt[n][k] = round(W[k][n] * sW).
// 32x32 smem tiles, block (32, 8), grid (32, 32, 3).
// ---------------------------------------------------------------------------
__global__ __launch_bounds__(256) void prep_w_kernel(
    const float* __restrict__ Wq, const float* __restrict__ Wk, const float* __restrict__ Wv)
{
    const int z = blockIdx.z;
    const float* W = (z == 0) ? Wq : (z == 1) ? Wk : Wv;
    const float sW = (z == 0) ? QSCALE : 1.0f;
    float* Wt = g_wt[z];

    __shared__ float tb[32][33];
    const int tx = threadIdx.x, ty = threadIdx.y;
    const int n0 = blockIdx.x * 32, k0 = blockIdx.y * 32;

    #pragma unroll
    for (int j = 0; j < 4; j++)
        tb[ty + j * 8][tx] = to_tf32(W[(size_t)(k0 + ty + j * 8) * DDIM + n0 + tx] * sW);
    __syncthreads();
    #pragma unroll
    for (int j = 0; j < 4; j++)
        Wt[(size_t)(n0 + ty + j * 8) * DDIM + k0 + tx] = tb[tx][ty + j * 8];
}

// ---------------------------------------------------------------------------
// Kernel 1: QKV projection GEMM — cp.async double-buffered + ldmatrix both
// operands.  CTA 128(M) x 128(N), BK=32, 256 thr = 8 warps (4M x 2N).
// Operands are pre-rounded (g_xr) / pre-rounded+transposed (g_wt), so the
// hot loop is raw bytes: cp.async -> ldmatrix -> mma.  Bit-identical math.
// z==2 (V) written transposed to [b][h][hd][s].
// ---------------------------------------------------------------------------
#define QP 36                       // smem pitch (== 4 mod 32: ldmatrix conflict-free)
#define QTILE (128 * QP)            // floats per operand tile
#define QSTAGE (2 * QTILE)          // X + W per stage
#define QKV_SMEM_BYTES (2 * QSTAGE * 4)   // 73,728 B
#define NKT (DDIM / 32)             // 32 k-tiles

__global__ __launch_bounds__(256, 2) void qkv_proj_kernel(
    const float* __restrict__ bq, const float* __restrict__ bk, const float* __restrict__ bv)
{
    extern __shared__ float smq[];
    const int z = blockIdx.z;
    const float* Xr = g_xr[z];
    const float* Wt = g_wt[z];
    const float* bias = (z == 0) ? bq : (z == 1) ? bk : bv;
    const float sW    = (z == 0) ? QSCALE : 1.0f;
    float* out = g_qkv[z];

    const int tid  = threadIdx.x;
    const int wid  = tid >> 5;
    const int lane = tid & 31;
    const int g    = lane >> 2;
    const int t    = lane & 3;
    const int wm   = wid & 3;
    const int wn   = wid >> 2;
    const int m0 = blockIdx.y * 128;
    const int n0 = blockIdx.x * 128;

    const uint32_t sbase = (uint32_t)__cvta_generic_to_shared(smq);

    // ldmatrix lane-offsets (bytes):
    // A tiles: [m0-7,kLo],[m8-15,kLo],[m0-7,kHi],[m8-15,kHi]
    const uint32_t lmA =
        (uint32_t)(((((lane >> 3) & 1) * 8) + (lane & 7)) * QP +
                   ((lane >> 4) & 1) * 4) * 4;
    // B tiles: [n(2j) rows,kLo],[n(2j) rows,kHi],[n(2j+1) rows,kLo],[n(2j+1) rows,kHi]
    const uint32_t lmB =
        (uint32_t)(((((lane >> 4) & 1) * 8) + (lane & 7)) * QP +
                   ((lane >> 3) & 1) * 4) * 4;

    // prologue: prefetch k-tile 0 into stage 0
    #pragma unroll
    for (int c = 0; c < 4; c++) {
        const int chunk = tid + c * 256;      // 0..1023
        const int row = chunk >> 3;           // 0..127
        const int qj  = chunk & 7;            // 16B chunk within 128B row
        cp16(sbase + (uint32_t)(row * QP + qj * 4) * 4,
             Xr + (size_t)(m0 + row) * DDIM + qj * 4);
        cp16(sbase + (uint32_t)(QTILE + row * QP + qj * 4) * 4,
             Wt + (size_t)(n0 + row) * DDIM + qj * 4);
    }
    asm volatile("cp.async.commit_group;\n" ::: "memory");

    float acc[2][8][4];
    #pragma unroll
    for (int mi = 0; mi < 2; mi++)
        #pragma unroll
        for (int nt = 0; nt < 8; nt++)
            #pragma unroll
            for (int i = 0; i < 4; i++) acc[mi][nt][i] = 0.0f;

    for (int T = 0; T < NKT; T++) {
        asm volatile("cp.async.wait_group 0;\n" ::: "memory");
        __syncthreads();

        const int st = T & 1;
        // prefetch next k-tile into the other stage (overlaps with mma)
        if (T + 1 < NKT) {
            const int k1 = (T + 1) * 32;
            const uint32_t sb = sbase + (uint32_t)((st ^ 1) * QSTAGE) * 4;
            #pragma unroll
            for (int c = 0; c < 4; c++) {
                const int chunk = tid + c * 256;
                const int row = chunk >> 3;
                const int qj  = chunk & 7;
                cp16(sb + (uint32_t)(row * QP + qj * 4) * 4,
                     Xr + (size_t)(m0 + row) * DDIM + k1 + qj * 4);
                cp16(sb + (uint32_t)(QTILE + row * QP + qj * 4) * 4,
                     Wt + (size_t)(n0 + row) * DDIM + k1 + qj * 4);
            }
            asm volatile("cp.async.commit_group;\n" ::: "memory");
        }

        const uint32_t Xb = sbase + (uint32_t)(st * QSTAGE) * 4 +
                            (uint32_t)(wm * 32 * QP) * 4 + lmA;
        const uint32_t Wb = sbase + (uint32_t)(st * QSTAGE + QTILE) * 4 +
                            (uint32_t)(wn * 64 * QP) * 4 + lmB;

        #pragma unroll
        for (int ks = 0; ks < 4; ks++) {
            const int kk = ks * 8;
            uint32_t a[2][4];
            ldsm4(a[0][0], a[0][1], a[0][2], a[0][3], Xb + (uint32_t)kk * 4);
            ldsm4(a[1][0], a[1][1], a[1][2], a[1][3],
                  Xb + (uint32_t)(16 * QP + kk) * 4);
            uint32_t b[8][2];
            #pragma unroll
            for (int j = 0; j < 4; j++)
                ldsm4(b[2*j][0], b[2*j][1], b[2*j+1][0], b[2*j+1][1],
                      Wb + (uint32_t)(j * 16 * QP + kk) * 4);
            #pragma unroll
            for (int mi = 0; mi < 2; mi++)
                #pragma unroll
                for (int nt = 0; nt < 8; nt++)
                    mma_tf32(acc[mi][nt], a[mi][0], a[mi][1], a[mi][2], a[mi][3],
                             b[nt][0], b[nt][1]);
        }
    }

    // epilogue: bias add, tf32 round, scatter
    #pragma unroll
    for (int mi = 0; mi < 2; mi++) {
        const int row0 = m0 + wm * 32 + mi * 16 + g;
        const int row1 = row0 + 8;
        #pragma unroll
        for (int nt = 0; nt < 8; nt++) {
            const int col = n0 + wn * 64 + nt * 8 + 2 * t;
            const float b0 = bias[col] * sW, b1 = bias[col + 1] * sW;
            const int h  = col >> 6;
            const int hd = col & 63;
            const int b_0 = row0 >> 11, s0 = row0 & 2047;
            const int b_1 = row1 >> 11, s1 = row1 & 2047;
            if (z < 2) {
                float2 v0 = make_float2(to_tf32(acc[mi][nt][0] + b0),
                                        to_tf32(acc[mi][nt][1] + b1));
                float2 v1 = make_float2(to_tf32(acc[mi][nt][2] + b0),
                                        to_tf32(acc[mi][nt][3] + b1));
                *reinterpret_cast<float2*>(
                    &out[(((size_t)b_0 * HH + h) * SS + s0) * HDD + hd]) = v0;
                *reinterpret_cast<float2*>(
                    &out[(((size_t)b_1 * HH + h) * SS + s1) * HDD + hd]) = v1;
            } else {
                const size_t base0 = ((size_t)b_0 * HH + h) * HDD;
                const size_t base1 = ((size_t)b_1 * HH + h) * HDD;
                out[(base0 + hd    ) * SS + s0] = to_tf32(acc[mi][nt][0] + b0);
                out[(base0 + hd + 1) * SS + s0] = to_tf32(acc[mi][nt][1] + b1);
                out[(base1 + hd    ) * SS + s1] = to_tf32(acc[mi][nt][2] + b0);
                out[(base1 + hd + 1) * SS + s1] = to_tf32(acc[mi][nt][3] + b1);
            }
        }
    }
}

// ---------------------------------------------------------------------------
// Kernel 2: flash attention (unchanged from round 10).
// cp.async double-buffered K/V, ldmatrix B-fragments, no-max log2 softmax.
// ---------------------------------------------------------------------------
#define KP 68
#define STG (64 * KP)
#define STAGE_STRIDE (2 * STG)
#define ATTN_SMEM_BYTES (2 * STAGE_STRIDE * 4)
#define NT (SS / 64)

__global__ __launch_bounds__(128, 3) void attn_kernel(float* __restrict__ out)
{
    extern __shared__ float sm[];

    const int tid  = threadIdx.x;
    const int wid  = tid >> 5;
    const int lane = tid & 31;
    const int g    = lane >> 2;
    const int t    = lane & 3;
    const int q0   = blockIdx.x * 64;
    const int bh   = blockIdx.y;
    const int wq   = wid * 16;

    const float* Qg = g_qkv[0] + (size_t)bh * SS * HDD;
    const float* Kg = g_qkv[1] + (size_t)bh * SS * HDD;
    const float* Vg = g_qkv[2] + (size_t)bh * HDD * SS;

    const uint32_t smem_u32 = (uint32_t)__cvta_generic_to_shared(sm);

    const uint32_t lm_off =
        (uint32_t)((((lane >> 4) & 1) * 8 + (lane & 7)) * KP +
                   ((lane >> 3) & 1) * 4) * 4;

    #pragma unroll
    for (int c = 0; c < 8; c++) {
        const int chunk = tid + c * 128;
        const int row = chunk >> 4;
        const int col = (chunk & 15) * 4;
        cp16(smem_u32 + (uint32_t)(row * KP + col) * 4,
             Kg + (size_t)row * HDD + col);
        cp16(smem_u32 + (uint32_t)(STG + row * KP + col) * 4,
             Vg + (size_t)row * SS + col);
    }
    asm volatile("cp.async.commit_group;\n" ::: "memory");

    float* Qstage = sm + STAGE_STRIDE;
    {
        const int c4 = (tid & 15) * 4;
        const int rb = tid >> 4;
        #pragma unroll
        for (int j = 0; j < 8; j++) {
            const int row = rb + j * 8;
            float4 v = *reinterpret_cast<const float4*>(
                &Qg[(size_t)(q0 + row) * HDD + c4]);
            *reinterpret_cast<float4*>(&Qstage[row * KP + c4]) = v;
        }
    }
    __syncthreads();
    uint32_t qf[8][4];
    #pragma unroll
    for (int ks = 0; ks < 8; ks++) {
        const int kk = ks * 8;
        qf[ks][0] = ldsf(&Qstage[(wq + g    ) * KP + kk + t    ]);
        qf[ks][1] = ldsf(&Qstage[(wq + 8 + g) * KP + kk + t    ]);
        qf[ks][2] = ldsf(&Qstage[(wq + g    ) * KP + kk + t + 4]);
        qf[ks][3] = ldsf(&Qstage[(wq + 8 + g) * KP + kk + t + 4]);
    }

    float o[8][4];
    float l_st0 = 0.0f, l_st1 = 0.0f;
    #pragma unroll
    for (int nt = 0; nt < 8; nt++)
        #pragma unroll
        for (int i = 0; i < 4; i++) o[nt][i] = 0.0f;

    const int src0 = (lane & 28) | ((lane >> 1) & 1);
    const int src1 = src0 + 2;
    const bool odd = (lane & 1);

    for (int T = 0; T < NT; T++) {
        asm volatile("cp.async.wait_group 0;\n" ::: "memory");
        __syncthreads();

        const int st = T & 1;
        const uint32_t Ksb_u32 = smem_u32 + (uint32_t)(st * STAGE_STRIDE) * 4 + lm_off;
        const uint32_t Vsb_u32 = Ksb_u32 + (uint32_t)STG * 4;

        if (T + 1 < NT) {
            const int kt1 = (T + 1) * 64;
            const uint32_t sb = smem_u32 + (uint32_t)((st ^ 1) * STAGE_STRIDE) * 4;
            #pragma unroll
            for (int c = 0; c < 8; c++) {
                const int chunk = tid + c * 128;
                const int row = chunk >> 4;
                const int col = (chunk & 15) * 4;
                cp16(sb + (uint32_t)(row * KP + col) * 4,
                     Kg + (size_t)(kt1 + row) * HDD + col);
                cp16(sb + (uint32_t)(STG + row * KP + col) * 4,
                     Vg + (size_t)row * SS + kt1 + col);
            }
            asm volatile("cp.async.commit_group;\n" ::: "memory");
        }

        float s[8][4];
        #pragma unroll
        for (int nt = 0; nt < 8; nt++)
            #pragma unroll
            for (int i = 0; i < 4; i++) s[nt][i] = 0.0f;

        #pragma unroll
        for (int ks = 0; ks < 8; ks++) {
            const int kk = ks * 8;
            uint32_t b[8][2];
            #pragma unroll
            for (int j = 0; j < 4; j++)
                ldsm4(b[2*j][0], b[2*j][1], b[2*j+1][0], b[2*j+1][1],
                      Ksb_u32 + (uint32_t)(j * 16 * KP + kk) * 4);
            #pragma unroll
            for (int nt = 0; nt < 8; nt++)
                mma_tf32(s[nt], qf[ks][0], qf[ks][1], qf[ks][2], qf[ks][3],
                         b[nt][0], b[nt][1]);
        }

        #pragma unroll
        for (int nt = 0; nt < 8; nt++) {
            s[nt][0] = ex2f(s[nt][0]);
            s[nt][1] = ex2f(s[nt][1]);
            s[nt][2] = ex2f(s[nt][2]);
            s[nt][3] = ex2f(s[nt][3]);
            l_st0 += s[nt][0] + s[nt][1];
            l_st1 += s[nt][2] + s[nt][3];
        }

        #pragma unroll
        for (int kt8 = 0; kt8 < 8; kt8++) {
            const float e0 = __shfl_sync(0xffffffffu, s[kt8][0], src0);
            const float e1 = __shfl_sync(0xffffffffu, s[kt8][1], src0);
            const float e2 = __shfl_sync(0xffffffffu, s[kt8][2], src0);
            const float e3 = __shfl_sync(0xffffffffu, s[kt8][3], src0);
            const float f0 = __shfl_sync(0xffffffffu, s[kt8][0], src1);
            const float f1 = __shfl_sync(0xffffffffu, s[kt8][1], src1);
            const float f2 = __shfl_sync(0xffffffffu, s[kt8][2], src1);
            const float f3 = __shfl_sync(0xffffffffu, s[kt8][3], src1);
            const uint32_t a0 = __float_as_uint(odd ? e1 : e0);
            const uint32_t a1 = __float_as_uint(odd ? e3 : e2);
            const uint32_t a2 = __float_as_uint(odd ? f1 : f0);
            const uint32_t a3 = __float_as_uint(odd ? f3 : f2);

            const int kk = kt8 * 8;
            uint32_t b[8][2];
            #pragma unroll
            for (int j = 0; j < 4; j++)
                ldsm4(b[2*j][0], b[2*j][1], b[2*j+1][0], b[2*j+1][1],
                      Vsb_u32 + (uint32_t)(j * 16 * KP + kk) * 4);
            #pragma unroll
            for (int nt = 0; nt < 8; nt++)
                mma_tf32(o[nt], a0, a1, a2, a3, b[nt][0], b[nt][1]);
        }
    }

    l_st0 += __shfl_xor_sync(0xffffffffu, l_st0, 1);
    l_st0 += __shfl_xor_sync(0xffffffffu, l_st0, 2);
    l_st1 += __shfl_xor_sync(0xffffffffu, l_st1, 1);
    l_st1 += __shfl_xor_sync(0xffffffffu, l_st1, 2);

    const int b_ = bh >> 4;
    const int h  = bh & 15;
    {
        const float inv0 = 1.0f / l_st0;
        const float inv1 = 1.0f / l_st1;
        const int s0 = q0 + wq + g;
        const int s1 = s0 + 8;
        #pragma unroll
        for (int nt = 0; nt < 8; nt++) {
            const int col = h * HDD + nt * 8 + 2 * t;
            float2 v0 = make_float2(o[nt][0] * inv0, o[nt][1] * inv0);
            float2 v1 = make_float2(o[nt][2] * inv1, o[nt][3] * inv1);
            *reinterpret_cast<float2*>(&out[((size_t)b_ * SS + s0) * DDIM + col]) = v0;
            *reinterpret_cast<float2*>(&out[((size_t)b_ * SS + s1) * DDIM + col]) = v1;
        }
    }
}

// ---------------------------------------------------------------------------
// Launch
// ---------------------------------------------------------------------------
extern "C" void kernel_launch(void* const* d_in, const int* in_sizes, int n_in,
                              void* d_out, int out_size)
{
    (void)in_sizes; (void)n_in; (void)out_size;
    const float* q  = (const float*)d_in[0];
    const float* k  = (const float*)d_in[1];
    const float* v  = (const float*)d_in[2];
    const float* Wq = (const float*)d_in[3];
    const float* bq = (const float*)d_in[4];
    const float* Wk = (const float*)d_in[5];
    const float* bk = (const float*)d_in[6];
    const float* Wv = (const float*)d_in[7];
    const float* bv = (const float*)d_in[8];
    float* out = (float*)d_out;

    // Pre-pass: rounded activations + transposed/rounded/scaled weights
    prep_x_kernel<<<dim3(4096, 3), 256>>>(q, k, v);
    prep_w_kernel<<<dim3(32, 32, 3), dim3(32, 8)>>>(Wq, Wk, Wv);

    // Projection GEMM
    cudaFuncSetAttribute(qkv_proj_kernel,
                         cudaFuncAttributeMaxDynamicSharedMemorySize,
                         QKV_SMEM_BYTES);   // 73,728 B
    qkv_proj_kernel<<<dim3(DDIM / 128, MM / 128, 3), 256, QKV_SMEM_BYTES>>>(bq, bk, bv);

    // Attention
    cudaFuncSetAttribute(attn_kernel,
                         cudaFuncAttributeMaxDynamicSharedMemorySize,
                         ATTN_SMEM_BYTES);   // 69,632 B
    attn_kernel<<<dim3(SS / 64, BB * HH), 128, ATTN_SMEM_BYTES>>>(out);
}

// round 14
// speedup vs baseline: 1.0248x; 1.0248x over previous
#include <cuda_runtime.h>
#include <math.h>
#include <stdint.h>

// Problem constants
#define BB   2
#define SS   2048
#define DDIM 1024
#define HH   16
#define HDD  64
#define MM   (BB*SS)   // 4096

// log2(e)/sqrt(HD): folded into Wq (via prep) and bq (epilogue)
#define QSCALE 0.18033688f

// Scratch:
//  g_qkv: Q,K in [b][h][s][hd]; V transposed [b][h][hd][s]  (tf32-rounded)
//  g_wt : transposed + rounded weights Wt[n][k] (Wq pre-scaled by QSCALE)
__device__ float g_qkv[3][(size_t)BB * HH * SS * HDD];
__device__ float g_wt [3][(size_t)DDIM * DDIM];

// ---------------------------------------------------------------------------
// helpers
// ---------------------------------------------------------------------------
__device__ __forceinline__ float to_tf32(float x) {
    uint32_t u;
    asm("cvt.rna.tf32.f32 %0, %1;" : "=r"(u) : "f"(x));
    return __uint_as_float(u);
}

// register-domain RNA rounding (same instruction, uint view)
__device__ __forceinline__ uint32_t rna_u32(uint32_t x) {
    uint32_t u;
    asm("cvt.rna.tf32.f32 %0, %1;" : "=r"(u) : "r"(x));
    return u;
}

__device__ __forceinline__ float ex2f(float x) {
    float y;
    asm("ex2.approx.ftz.f32 %0, %1;" : "=f"(y) : "f"(x));
    return y;
}

__device__ __forceinline__ void mma_tf32(float c[4],
                                         uint32_t a0, uint32_t a1, uint32_t a2, uint32_t a3,
                                         uint32_t b0, uint32_t b1) {
    asm volatile(
        "mma.sync.aligned.m16n8k8.row.col.f32.tf32.tf32.f32 "
        "{%0,%1,%2,%3}, {%4,%5,%6,%7}, {%8,%9}, {%0,%1,%2,%3};"
        : "+f"(c[0]), "+f"(c[1]), "+f"(c[2]), "+f"(c[3])
        : "r"(a0), "r"(a1), "r"(a2), "r"(a3), "r"(b0), "r"(b1));
}

__device__ __forceinline__ uint32_t ldsf(const float* p) {
    return __float_as_uint(*p);
}

__device__ __forceinline__ void ldsm4(uint32_t& r0, uint32_t& r1,
                                      uint32_t& r2, uint32_t& r3, uint32_t addr) {
    asm volatile("ldmatrix.sync.aligned.m8n8.x4.shared.b16 {%0,%1,%2,%3}, [%4];"
                 : "=r"(r0), "=r"(r1), "=r"(r2), "=r"(r3) : "r"(addr));
}

__device__ __forceinline__ void cp16(uint32_t smem_dst, const void* gsrc) {
    asm volatile("cp.async.cg.shared.global [%0], [%1], 16;\n"
                 :: "r"(smem_dst), "l"(gsrc) : "memory");
}

// ---------------------------------------------------------------------------
// Pre-pass: transpose + round weights:  Wt[n][k] = round(W[k][n] * sW).
// 32x32 smem tiles, block (32, 8), grid (32, 32, 3).
// ---------------------------------------------------------------------------
__global__ __launch_bounds__(256) void prep_w_kernel(
    const float* __restrict__ Wq, const float* __restrict__ Wk, const float* __restrict__ Wv)
{
    const int z = blockIdx.z;
    const float* W = (z == 0) ? Wq : (z == 1) ? Wk : Wv;
    const float sW = (z == 0) ? QSCALE : 1.0f;
    float* Wt = g_wt[z];

    __shared__ float tb[32][33];
    const int tx = threadIdx.x, ty = threadIdx.y;
    const int n0 = blockIdx.x * 32, k0 = blockIdx.y * 32;

    #pragma unroll
    for (int j = 0; j < 4; j++)
        tb[ty + j * 8][tx] = to_tf32(W[(size_t)(k0 + ty + j * 8) * DDIM + n0 + tx] * sW);
    __syncthreads();
    #pragma unroll
    for (int j = 0; j < 4; j++)
        Wt[(size_t)(n0 + ty + j * 8) * DDIM + k0 + tx] = tb[tx][ty + j * 8];
}

// ---------------------------------------------------------------------------
// Kernel 1: QKV projection GEMM — cp.async double-buffered + ldmatrix both
// operands.  CTA 128(M) x 128(N), BK=32, 256 thr = 8 warps (4M x 2N).
// A streamed RAW from the inputs; RNA-rounded IN REGISTERS post-ldmatrix
// (HW truncation alone is biased -> coherent error growth over K=1024;
// round 13 failed at 1.36e-3.  cvt.rna on the fragments restores round-12's
// exact arithmetic at ~32 CVT/k-tile/thread instead of a 35us prep pass).
// B from pre-transposed/rounded g_wt.
// z==2 (V) written transposed to [b][h][hd][s].
// ---------------------------------------------------------------------------
#define QP 36                       // smem pitch (== 4 mod 32: ldmatrix conflict-free)
#define QTILE (128 * QP)            // floats per operand tile
#define QSTAGE (2 * QTILE)          // X + W per stage
#define QKV_SMEM_BYTES (2 * QSTAGE * 4)   // 73,728 B
#define NKT (DDIM / 32)             // 32 k-tiles

__global__ __launch_bounds__(256, 2) void qkv_proj_kernel(
    const float* __restrict__ q, const float* __restrict__ k, const float* __restrict__ v,
    const float* __restrict__ bq, const float* __restrict__ bk, const float* __restrict__ bv)
{
    extern __shared__ float smq[];
    const int z = blockIdx.z;
    const float* Xr = (z == 0) ? q : (z == 1) ? k : v;   // raw fp32 activations
    const float* Wt = g_wt[z];
    const float* bias = (z == 0) ? bq : (z == 1) ? bk : bv;
    const float sW    = (z == 0) ? QSCALE : 1.0f;
    float* out = g_qkv[z];

    const int tid  = threadIdx.x;
    const int wid  = tid >> 5;
    const int lane = tid & 31;
    const int g    = lane >> 2;
    const int t    = lane & 3;
    const int wm   = wid & 3;
    const int wn   = wid >> 2;
    const int m0 = blockIdx.y * 128;
    const int n0 = blockIdx.x * 128;

    const uint32_t sbase = (uint32_t)__cvta_generic_to_shared(smq);

    // ldmatrix lane-offsets (bytes):
    // A tiles: [m0-7,kLo],[m8-15,kLo],[m0-7,kHi],[m8-15,kHi]
    const uint32_t lmA =
        (uint32_t)(((((lane >> 3) & 1) * 8) + (lane & 7)) * QP +
                   ((lane >> 4) & 1) * 4) * 4;
    // B tiles: [n(2j) rows,kLo],[n(2j) rows,kHi],[n(2j+1) rows,kLo],[n(2j+1) rows,kHi]
    const uint32_t lmB =
        (uint32_t)(((((lane >> 4) & 1) * 8) + (lane & 7)) * QP +
                   ((lane >> 3) & 1) * 4) * 4;

    // prologue: prefetch k-tile 0 into stage 0
    #pragma unroll
    for (int c = 0; c < 4; c++) {
        const int chunk = tid + c * 256;      // 0..1023
        const int row = chunk >> 3;           // 0..127
        const int qj  = chunk & 7;            // 16B chunk within 128B row
        cp16(sbase + (uint32_t)(row * QP + qj * 4) * 4,
             Xr + (size_t)(m0 + row) * DDIM + qj * 4);
        cp16(sbase + (uint32_t)(QTILE + row * QP + qj * 4) * 4,
             Wt + (size_t)(n0 + row) * DDIM + qj * 4);
    }
    asm volatile("cp.async.commit_group;\n" ::: "memory");

    float acc[2][8][4];
    #pragma unroll
    for (int mi = 0; mi < 2; mi++)
        #pragma unroll
        for (int nt = 0; nt < 8; nt++)
            #pragma unroll
            for (int i = 0; i < 4; i++) acc[mi][nt][i] = 0.0f;

    for (int T = 0; T < NKT; T++) {
        asm volatile("cp.async.wait_group 0;\n" ::: "memory");
        __syncthreads();

        const int st = T & 1;
        // prefetch next k-tile into the other stage (overlaps with mma)
        if (T + 1 < NKT) {
            const int k1 = (T + 1) * 32;
            const uint32_t sb = sbase + (uint32_t)((st ^ 1) * QSTAGE) * 4;
            #pragma unroll
            for (int c = 0; c < 4; c++) {
                const int chunk = tid + c * 256;
                const int row = chunk >> 3;
                const int qj  = chunk & 7;
                cp16(sb + (uint32_t)(row * QP + qj * 4) * 4,
                     Xr + (size_t)(m0 + row) * DDIM + k1 + qj * 4);
                cp16(sb + (uint32_t)(QTILE + row * QP + qj * 4) * 4,
                     Wt + (size_t)(n0 + row) * DDIM + k1 + qj * 4);
            }
            asm volatile("cp.async.commit_group;\n" ::: "memory");
        }

        const uint32_t Xb = sbase + (uint32_t)(st * QSTAGE) * 4 +
                            (uint32_t)(wm * 32 * QP) * 4 + lmA;
        const uint32_t Wb = sbase + (uint32_t)(st * QSTAGE + QTILE) * 4 +
                            (uint32_t)(wn * 64 * QP) * 4 + lmB;

        #pragma unroll
        for (int ks = 0; ks < 4; ks++) {
            const int kk = ks * 8;
            uint32_t a[2][4];
            ldsm4(a[0][0], a[0][1], a[0][2], a[0][3], Xb + (uint32_t)kk * 4);
            ldsm4(a[1][0], a[1][1], a[1][2], a[1][3],
                  Xb + (uint32_t)(16 * QP + kk) * 4);
            // RNA-round the A fragments (B is pre-rounded in memory)
            #pragma unroll
            for (int mi = 0; mi < 2; mi++)
                #pragma unroll
                for (int i = 0; i < 4; i++)
                    a[mi][i] = rna_u32(a[mi][i]);
            uint32_t b[8][2];
            #pragma unroll
            for (int j = 0; j < 4; j++)
                ldsm4(b[2*j][0], b[2*j][1], b[2*j+1][0], b[2*j+1][1],
                      Wb + (uint32_t)(j * 16 * QP + kk) * 4);
            #pragma unroll
            for (int mi = 0; mi < 2; mi++)
                #pragma unroll
                for (int nt = 0; nt < 8; nt++)
                    mma_tf32(acc[mi][nt], a[mi][0], a[mi][1], a[mi][2], a[mi][3],
                             b[nt][0], b[nt][1]);
        }
    }

    // epilogue: bias add, tf32 round, scatter
    #pragma unroll
    for (int mi = 0; mi < 2; mi++) {
        const int row0 = m0 + wm * 32 + mi * 16 + g;
        const int row1 = row0 + 8;
        #pragma unroll
        for (int nt = 0; nt < 8; nt++) {
            const int col = n0 + wn * 64 + nt * 8 + 2 * t;
            const float b0 = bias[col] * sW, b1 = bias[col + 1] * sW;
            const int h  = col >> 6;
            const int hd = col & 63;
            const int b_0 = row0 >> 11, s0 = row0 & 2047;
            const int b_1 = row1 >> 11, s1 = row1 & 2047;
            if (z < 2) {
                float2 v0 = make_float2(to_tf32(acc[mi][nt][0] + b0),
                                        to_tf32(acc[mi][nt][1] + b1));
                float2 v1 = make_float2(to_tf32(acc[mi][nt][2] + b0),
                                        to_tf32(acc[mi][nt][3] + b1));
                *reinterpret_cast<float2*>(
                    &out[(((size_t)b_0 * HH + h) * SS + s0) * HDD + hd]) = v0;
                *reinterpret_cast<float2*>(
                    &out[(((size_t)b_1 * HH + h) * SS + s1) * HDD + hd]) = v1;
            } else {
                const size_t base0 = ((size_t)b_0 * HH + h) * HDD;
                const size_t base1 = ((size_t)b_1 * HH + h) * HDD;
                out[(base0 + hd    ) * SS + s0] = to_tf32(acc[mi][nt][0] + b0);
                out[(base0 + hd + 1) * SS + s0] = to_tf32(acc[mi][nt][1] + b1);
                out[(base1 + hd    ) * SS + s1] = to_tf32(acc[mi][nt][2] + b0);
                out[(base1 + hd + 1) * SS + s1] = to_tf32(acc[mi][nt][3] + b1);
            }
        }
    }
}

// ---------------------------------------------------------------------------
// Kernel 2: flash attention (unchanged from round 10/12).
// cp.async double-buffered K/V, ldmatrix B-fragments, no-max log2 softmax.
// ---------------------------------------------------------------------------
#define KP 68
#define STG (64 * KP)
#define STAGE_STRIDE (2 * STG)
#define ATTN_SMEM_BYTES (2 * STAGE_STRIDE * 4)
#define NT (SS / 64)

__global__ __launch_bounds__(128, 3) void attn_kernel(float* __restrict__ out)
{
    extern __shared__ float sm[];

    const int tid  = threadIdx.x;
    const int wid  = tid >> 5;
    const int lane = tid & 31;
    const int g    = lane >> 2;
    const int t    = lane & 3;
    const int q0   = blockIdx.x * 64;
    const int bh   = blockIdx.y;
    const int wq   = wid * 16;

    const float* Qg = g_qkv[0] + (size_t)bh * SS * HDD;
    const float* Kg = g_qkv[1] + (size_t)bh * SS * HDD;
    const float* Vg = g_qkv[2] + (size_t)bh * HDD * SS;

    const uint32_t smem_u32 = (uint32_t)__cvta_generic_to_shared(sm);

    const uint32_t lm_off =
        (uint32_t)((((lane >> 4) & 1) * 8 + (lane & 7)) * KP +
                   ((lane >> 3) & 1) * 4) * 4;

    #pragma unroll
    for (int c = 0; c < 8; c++) {
        const int chunk = tid + c * 128;
        const int row = chunk >> 4;
        const int col = (chunk & 15) * 4;
        cp16(smem_u32 + (uint32_t)(row * KP + col) * 4,
             Kg + (size_t)row * HDD + col);
        cp16(smem_u32 + (uint32_t)(STG + row * KP + col) * 4,
             Vg + (size_t)row * SS + col);
    }
    asm volatile("cp.async.commit_group;\n" ::: "memory");

    float* Qstage = sm + STAGE_STRIDE;
    {
        const int c4 = (tid & 15) * 4;
        const int rb = tid >> 4;
        #pragma unroll
        for (int j = 0; j < 8; j++) {
            const int row = rb + j * 8;
            float4 v = *reinterpret_cast<const float4*>(
                &Qg[(size_t)(q0 + row) * HDD + c4]);
            *reinterpret_cast<float4*>(&Qstage[row * KP + c4]) = v;
        }
    }
    __syncthreads();
    uint32_t qf[8][4];
    #pragma unroll
    for (int ks = 0; ks < 8; ks++) {
        const int kk = ks * 8;
        qf[ks][0] = ldsf(&Qstage[(wq + g    ) * KP + kk + t    ]);
        qf[ks][1] = ldsf(&Qstage[(wq + 8 + g) * KP + kk + t    ]);
        qf[ks][2] = ldsf(&Qstage[(wq + g    ) * KP + kk + t + 4]);
        qf[ks][3] = ldsf(&Qstage[(wq + 8 + g) * KP + kk + t + 4]);
    }

    float o[8][4];
    float l_st0 = 0.0f, l_st1 = 0.0f;
    #pragma unroll
    for (int nt = 0; nt < 8; nt++)
        #pragma unroll
        for (int i = 0; i < 4; i++) o[nt][i] = 0.0f;

    const int src0 = (lane & 28) | ((lane >> 1) & 1);
    const int src1 = src0 + 2;
    const bool odd = (lane & 1);

    for (int T = 0; T < NT; T++) {
        asm volatile("cp.async.wait_group 0;\n" ::: "memory");
        __syncthreads();

        const int st = T & 1;
        const uint32_t Ksb_u32 = smem_u32 + (uint32_t)(st * STAGE_STRIDE) * 4 + lm_off;
        const uint32_t Vsb_u32 = Ksb_u32 + (uint32_t)STG * 4;

        if (T + 1 < NT) {
            const int kt1 = (T + 1) * 64;
            const uint32_t sb = smem_u32 + (uint32_t)((st ^ 1) * STAGE_STRIDE) * 4;
            #pragma unroll
            for (int c = 0; c < 8; c++) {
                const int chunk = tid + c * 128;
                const int row = chunk >> 4;
                const int col = (chunk & 15) * 4;
                cp16(sb + (uint32_t)(row * KP + col) * 4,
                     Kg + (size_t)(kt1 + row) * HDD + col);
                cp16(sb + (uint32_t)(STG + row * KP + col) * 4,
                     Vg + (size_t)row * SS + kt1 + col);
            }
            asm volatile("cp.async.commit_group;\n" ::: "memory");
        }

        float s[8][4];
        #pragma unroll
        for (int nt = 0; nt < 8; nt++)
            #pragma unroll
            for (int i = 0; i < 4; i++) s[nt][i] = 0.0f;

        #pragma unroll
        for (int ks = 0; ks < 8; ks++) {
            const int kk = ks * 8;
            uint32_t b[8][2];
            #pragma unroll
            for (int j = 0; j < 4; j++)
                ldsm4(b[2*j][0], b[2*j][1], b[2*j+1][0], b[2*j+1][1],
                      Ksb_u32 + (uint32_t)(j * 16 * KP + kk) * 4);
            #pragma unroll
            for (int nt = 0; nt < 8; nt++)
                mma_tf32(s[nt], qf[ks][0], qf[ks][1], qf[ks][2], qf[ks][3],
                         b[nt][0], b[nt][1]);
        }

        #pragma unroll
        for (int nt = 0; nt < 8; nt++) {
            s[nt][0] = ex2f(s[nt][0]);
            s[nt][1] = ex2f(s[nt][1]);
            s[nt][2] = ex2f(s[nt][2]);
            s[nt][3] = ex2f(s[nt][3]);
            l_st0 += s[nt][0] + s[nt][1];
            l_st1 += s[nt][2] + s[nt][3];
        }

        #pragma unroll
        for (int kt8 = 0; kt8 < 8; kt8++) {
            const float e0 = __shfl_sync(0xffffffffu, s[kt8][0], src0);
            const float e1 = __shfl_sync(0xffffffffu, s[kt8][1], src0);
            const float e2 = __shfl_sync(0xffffffffu, s[kt8][2], src0);
            const float e3 = __shfl_sync(0xffffffffu, s[kt8][3], src0);
            const float f0 = __shfl_sync(0xffffffffu, s[kt8][0], src1);
            const float f1 = __shfl_sync(0xffffffffu, s[kt8][1], src1);
            const float f2 = __shfl_sync(0xffffffffu, s[kt8][2], src1);
            const float f3 = __shfl_sync(0xffffffffu, s[kt8][3], src1);
            const uint32_t a0 = __float_as_uint(odd ? e1 : e0);
            const uint32_t a1 = __float_as_uint(odd ? e3 : e2);
            const uint32_t a2 = __float_as_uint(odd ? f1 : f0);
            const uint32_t a3 = __float_as_uint(odd ? f3 : f2);

            const int kk = kt8 * 8;
            uint32_t b[8][2];
            #pragma unroll
            for (int j = 0; j < 4; j++)
                ldsm4(b[2*j][0], b[2*j][1], b[2*j+1][0], b[2*j+1][1],
                      Vsb_u32 + (uint32_t)(j * 16 * KP + kk) * 4);
            #pragma unroll
            for (int nt = 0; nt < 8; nt++)
                mma_tf32(o[nt], a0, a1, a2, a3, b[nt][0], b[nt][1]);
        }
    }

    l_st0 += __shfl_xor_sync(0xffffffffu, l_st0, 1);
    l_st0 += __shfl_xor_sync(0xffffffffu, l_st0, 2);
    l_st1 += __shfl_xor_sync(0xffffffffu, l_st1, 1);
    l_st1 += __shfl_xor_sync(0xffffffffu, l_st1, 2);

    const int b_ = bh >> 4;
    const int h  = bh & 15;
    {
        const float inv0 = 1.0f / l_st0;
        const float inv1 = 1.0f / l_st1;
        const int s0 = q0 + wq + g;
        const int s1 = s0 + 8;
        #pragma unroll
        for (int nt = 0; nt < 8; nt++) {
            const int col = h * HDD + nt * 8 + 2 * t;
            float2 v0 = make_float2(o[nt][0] * inv0, o[nt][1] * inv0);
            float2 v1 = make_float2(o[nt][2] * inv1, o[nt][3] * inv1);
            *reinterpret_cast<float2*>(&out[((size_t)b_ * SS + s0) * DDIM + col]) = v0;
            *reinterpret_cast<float2*>(&out[((size_t)b_ * SS + s1) * DDIM + col]) = v1;
        }
    }
}

// ---------------------------------------------------------------------------
// Launch
// ---------------------------------------------------------------------------
extern "C" void kernel_launch(void* const* d_in, const int* in_sizes, int n_in,
                              void* d_out, int out_size)
{
    (void)in_sizes; (void)n_in; (void)out_size;
    const float* q  = (const float*)d_in[0];
    const float* k  = (const float*)d_in[1];
    const float* v  = (const float*)d_in[2];
    const float* Wq = (const float*)d_in[3];
    const float* bq = (const float*)d_in[4];
    const float* Wk = (const float*)d_in[5];
    const float* bk = (const float*)d_in[6];
    const float* Wv = (const float*)d_in[7];
    const float* bv = (const float*)d_in[8];
    float* out = (float*)d_out;

    // Pre-pass: transposed/rounded/scaled weights only (activations raw)
    prep_w_kernel<<<dim3(32, 32, 3), dim3(32, 8)>>>(Wq, Wk, Wv);

    // Projection GEMM
    cudaFuncSetAttribute(qkv_proj_kernel,
                         cudaFuncAttributeMaxDynamicSharedMemorySize,
                         QKV_SMEM_BYTES);   // 73,728 B
    qkv_proj_kernel<<<dim3(DDIM / 128, MM / 128, 3), 256, QKV_SMEM_BYTES>>>(
        q, k, v, bq, bk, bv);

    // Attention
    cudaFuncSetAttribute(attn_kernel,
                         cudaFuncAttributeMaxDynamicSharedMemorySize,
                         ATTN_SMEM_BYTES);   // 69,632 B
    attn_kernel<<<dim3(SS / 64, BB * HH), 128, ATTN_SMEM_BYTES>>>(out);
}

// round 15
// speedup vs baseline: 1.8789x; 1.8334x over previous
#include <cuda_runtime.h>
#include <cuda_fp16.h>
#include <math.h>
#include <stdint.h>

// Problem constants
#define BB   2
#define SS   2048
#define DDIM 1024
#define HH   16
#define HDD  64
#define MM   (BB*SS)   // 4096

// log2(e)/sqrt(HD): folded into Wq (via prep) and bq (epilogue)
#define QSCALE 0.18033688f
// log2-domain shift before ex2: bounds p=2^(s-SHIFT) << fp16 max; cancels in softmax
#define SHIFT 12.0f

// Scratch (all fp16):
//  g_qkvh: Q,K in [b][h][s][hd]; V transposed [b][h][hd][s]
//  g_xh  : fp16 copies of raw activations [m][d]
//  g_wth : transposed fp16 weights Wt[n][k] (Wq pre-scaled by QSCALE)
__device__ __half g_qkvh[3][(size_t)BB * HH * SS * HDD];
__device__ __half g_xh  [3][(size_t)MM * DDIM];
__device__ __half g_wth [3][(size_t)DDIM * DDIM];

// ---------------------------------------------------------------------------
// helpers
// ---------------------------------------------------------------------------
__device__ __forceinline__ float ex2f(float x) {
    float y;
    asm("ex2.approx.ftz.f32 %0, %1;" : "=f"(y) : "f"(x));
    return y;
}

// pack two f32 into f16x2: lo half = 'lo', hi half = 'hi' (first PTX src -> hi)
__device__ __forceinline__ uint32_t pack_f16(float hi, float lo) {
    uint32_t d;
    asm("cvt.rn.f16x2.f32 %0, %1, %2;" : "=r"(d) : "f"(hi), "f"(lo));
    return d;
}

__device__ __forceinline__ void mma_f16(float c[4],
                                        uint32_t a0, uint32_t a1, uint32_t a2, uint32_t a3,
                                        uint32_t b0, uint32_t b1) {
    asm volatile(
        "mma.sync.aligned.m16n8k16.row.col.f32.f16.f16.f32 "
        "{%0,%1,%2,%3}, {%4,%5,%6,%7}, {%8,%9}, {%0,%1,%2,%3};"
        : "+f"(c[0]), "+f"(c[1]), "+f"(c[2]), "+f"(c[3])
        : "r"(a0), "r"(a1), "r"(a2), "r"(a3), "r"(b0), "r"(b1));
}

__device__ __forceinline__ void ldsm4(uint32_t& r0, uint32_t& r1,
                                      uint32_t& r2, uint32_t& r3, uint32_t addr) {
    asm volatile("ldmatrix.sync.aligned.m8n8.x4.shared.b16 {%0,%1,%2,%3}, [%4];"
                 : "=r"(r0), "=r"(r1), "=r"(r2), "=r"(r3) : "r"(addr));
}

__device__ __forceinline__ void cp16(uint32_t smem_dst, const void* gsrc) {
    asm volatile("cp.async.cg.shared.global [%0], [%1], 16;\n"
                 :: "r"(smem_dst), "l"(gsrc) : "memory");
}

// ---------------------------------------------------------------------------
// Pre-pass A: fp32 -> fp16 activations.  grid (4096, 3) x 256, 4 elems/thread.
// ---------------------------------------------------------------------------
__global__ __launch_bounds__(256) void prep_x_kernel(
    const float* __restrict__ q, const float* __restrict__ k, const float* __restrict__ v)
{
    const int z = blockIdx.y;
    const float* src = (z == 0) ? q : (z == 1) ? k : v;
    __half* dst = g_xh[z];
    const size_t i = ((size_t)blockIdx.x * 256 + threadIdx.x) * 4;
    float4 val = *reinterpret_cast<const float4*>(src + i);
    *reinterpret_cast<__half2*>(dst + i)     = __floats2half2_rn(val.x, val.y);
    *reinterpret_cast<__half2*>(dst + i + 2) = __floats2half2_rn(val.z, val.w);
}

// ---------------------------------------------------------------------------
// Pre-pass B: transpose + fp16:  Wt[n][k] = half(W[k][n] * sW).
// ---------------------------------------------------------------------------
__global__ __launch_bounds__(256) void prep_w_kernel(
    const float* __restrict__ Wq, const float* __restrict__ Wk, const float* __restrict__ Wv)
{
    const int z = blockIdx.z;
    const float* W = (z == 0) ? Wq : (z == 1) ? Wk : Wv;
    const float sW = (z == 0) ? QSCALE : 1.0f;
    __half* Wt = g_wth[z];

    __shared__ float tb[32][33];
    const int tx = threadIdx.x, ty = threadIdx.y;
    const int n0 = blockIdx.x * 32, k0 = blockIdx.y * 32;

    #pragma unroll
    for (int j = 0; j < 4; j++)
        tb[ty + j * 8][tx] = W[(size_t)(k0 + ty + j * 8) * DDIM + n0 + tx] * sW;
    __syncthreads();
    #pragma unroll
    for (int j = 0; j < 4; j++)
        Wt[(size_t)(n0 + ty + j * 8) * DDIM + k0 + tx] = __float2half(tb[tx][ty + j * 8]);
}

// ---------------------------------------------------------------------------
// Shared ldmatrix geometry: rows of 144 bytes (72 halfs, pitch conflict-free:
// 8 consecutive rows hit the 8 distinct 16B bank groups).
// A-frag (m16k16): tiles [g rows,k0-7],[g+8,k0-7],[g,k8-15],[g+8,k8-15]
// B-frag (k16n8 pairs): tiles [n0-7,k0-7],[n0-7,k8-15],[n8-15,k0-7],[n8-15,k8-15]
// ---------------------------------------------------------------------------
#define RB 144   // row bytes (72 halfs)

// ---------------------------------------------------------------------------
// Kernel 1: QKV projection GEMM, fp16 m16n8k16.
// CTA 128(M) x 128(N), BK=64 (4 k16 steps), 256 thr = 8 warps (4M x 2N).
// cp.async double-buffered; both operands via ldmatrix.
// z==2 (V) written transposed to [b][h][hd][s].
// ---------------------------------------------------------------------------
#define GTILE_B (128 * RB)            // 18,432 B per operand tile
#define GSTAGE_B (2 * GTILE_B)        // X + W per stage
#define QKV_SMEM_BYTES (2 * GSTAGE_B) // 73,728 B
#define NKT (DDIM / 64)               // 16 k-tiles

__global__ __launch_bounds__(256, 2) void qkv_proj_kernel(
    const float* __restrict__ bq, const float* __restrict__ bk, const float* __restrict__ bv)
{
    extern __shared__ __half smh[];
    const int z = blockIdx.z;
    const __half* Xh = g_xh[z];
    const __half* Wth = g_wth[z];
    const float* bias = (z == 0) ? bq : (z == 1) ? bk : bv;
    const float sW    = (z == 0) ? QSCALE : 1.0f;
    __half* out = g_qkvh[z];

    const int tid  = threadIdx.x;
    const int wid  = tid >> 5;
    const int lane = tid & 31;
    const int g    = lane >> 2;
    const int t    = lane & 3;
    const int wm   = wid & 3;
    const int wn   = wid >> 2;
    const int m0 = blockIdx.y * 128;
    const int n0 = blockIdx.x * 128;

    const uint32_t sbase = (uint32_t)__cvta_generic_to_shared(smh);

    const uint32_t lmA =
        (uint32_t)((lane & 7) + ((lane >> 3) & 1) * 8) * RB + ((lane >> 4) & 1) * 16;
    const uint32_t lmB =
        (uint32_t)((lane & 7) + ((lane >> 4) & 1) * 8) * RB + ((lane >> 3) & 1) * 16;

    // prologue: prefetch k-tile 0 into stage 0 (X and W tiles: 128 rows x 64 halfs)
    #pragma unroll
    for (int c = 0; c < 4; c++) {
        const int chunk = tid + c * 256;      // 0..1023
        const int row = chunk >> 3;           // 0..127
        const int qb  = chunk & 7;            // 16B chunk (8 halfs)
        cp16(sbase + (uint32_t)row * RB + qb * 16,
             Xh + (size_t)(m0 + row) * DDIM + qb * 8);
        cp16(sbase + GTILE_B + (uint32_t)row * RB + qb * 16,
             Wth + (size_t)(n0 + row) * DDIM + qb * 8);
    }
    asm volatile("cp.async.commit_group;\n" ::: "memory");

    float acc[2][8][4];
    #pragma unroll
    for (int mi = 0; mi < 2; mi++)
        #pragma unroll
        for (int nt = 0; nt < 8; nt++)
            #pragma unroll
            for (int i = 0; i < 4; i++) acc[mi][nt][i] = 0.0f;

    for (int T = 0; T < NKT; T++) {
        asm volatile("cp.async.wait_group 0;\n" ::: "memory");
        __syncthreads();

        const int st = T & 1;
        if (T + 1 < NKT) {
            const int k1 = (T + 1) * 64;
            const uint32_t sb = sbase + (uint32_t)((st ^ 1) * GSTAGE_B);
            #pragma unroll
            for (int c = 0; c < 4; c++) {
                const int chunk = tid + c * 256;
                const int row = chunk >> 3;
                const int qb  = chunk & 7;
                cp16(sb + (uint32_t)row * RB + qb * 16,
                     Xh + (size_t)(m0 + row) * DDIM + k1 + qb * 8);
                cp16(sb + GTILE_B + (uint32_t)row * RB + qb * 16,
                     Wth + (size_t)(n0 + row) * DDIM + k1 + qb * 8);
            }
            asm volatile("cp.async.commit_group;\n" ::: "memory");
        }

        const uint32_t Xb = sbase + (uint32_t)(st * GSTAGE_B) +
                            (uint32_t)(wm * 32) * RB + lmA;
        const uint32_t Wb = sbase + (uint32_t)(st * GSTAGE_B + GTILE_B) +
                            (uint32_t)(wn * 64) * RB + lmB;

        #pragma unroll
        for (int ks = 0; ks < 4; ks++) {
            const uint32_t koff = ks * 32;     // 16 halfs
            uint32_t a[2][4];
            #pragma unroll
            for (int mi = 0; mi < 2; mi++)
                ldsm4(a[mi][0], a[mi][1], a[mi][2], a[mi][3],
                      Xb + (uint32_t)(mi * 16) * RB + koff);
            uint32_t b[8][2];
            #pragma unroll
            for (int j = 0; j < 4; j++)
                ldsm4(b[2*j][0], b[2*j][1], b[2*j+1][0], b[2*j+1][1],
                      Wb + (uint32_t)(j * 16) * RB + koff);
            #pragma unroll
            for (int mi = 0; mi < 2; mi++)
                #pragma unroll
                for (int nt = 0; nt < 8; nt++)
                    mma_f16(acc[mi][nt], a[mi][0], a[mi][1], a[mi][2], a[mi][3],
                            b[nt][0], b[nt][1]);
        }
    }

    // epilogue: bias add, fp16 round, scatter
    #pragma unroll
    for (int mi = 0; mi < 2; mi++) {
        const int row0 = m0 + wm * 32 + mi * 16 + g;
        const int row1 = row0 + 8;
        #pragma unroll
        for (int nt = 0; nt < 8; nt++) {
            const int col = n0 + wn * 64 + nt * 8 + 2 * t;
            const float b0 = bias[col] * sW, b1 = bias[col + 1] * sW;
            const int h  = col >> 6;
            const int hd = col & 63;
            const int b_0 = row0 >> 11, s0 = row0 & 2047;
            const int b_1 = row1 >> 11, s1 = row1 & 2047;
            if (z < 2) {
                __half2 v0 = __floats2half2_rn(acc[mi][nt][0] + b0, acc[mi][nt][1] + b1);
                __half2 v1 = __floats2half2_rn(acc[mi][nt][2] + b0, acc[mi][nt][3] + b1);
                *reinterpret_cast<__half2*>(
                    &out[(((size_t)b_0 * HH + h) * SS + s0) * HDD + hd]) = v0;
                *reinterpret_cast<__half2*>(
                    &out[(((size_t)b_1 * HH + h) * SS + s1) * HDD + hd]) = v1;
            } else {
                const size_t base0 = ((size_t)b_0 * HH + h) * HDD;
                const size_t base1 = ((size_t)b_1 * HH + h) * HDD;
                out[(base0 + hd    ) * SS + s0] = __float2half(acc[mi][nt][0] + b0);
                out[(base0 + hd + 1) * SS + s0] = __float2half(acc[mi][nt][1] + b1);
                out[(base1 + hd    ) * SS + s1] = __float2half(acc[mi][nt][2] + b0);
                out[(base1 + hd + 1) * SS + s1] = __float2half(acc[mi][nt][3] + b1);
            }
        }
    }
}

// ---------------------------------------------------------------------------
// Kernel 2: flash attention, fp16 m16n8k16, cp.async double-buffered.
// CTA = 64 queries of one (b,h); 4 warps, 16 q/warp.  grid = (32, 32).
// No-max softmax with fixed SHIFT; P->A conversion is lane-local f16x2 packs
// (fp16 QK C-layout holds adjacent key pairs = exactly the k16 A-layout).
// ---------------------------------------------------------------------------
#define STG_B (64 * RB)              // 9,216 B per K-or-V tile
#define STAGE_B (2 * STG_B)          // K+V per stage
#define ATTN_SMEM_BYTES (2 * STAGE_B)  // 36,864 B
#define NT (SS / 64)                 // 32 key tiles

__global__ __launch_bounds__(128, 3) void attn_kernel(float* __restrict__ out)
{
    extern __shared__ __half smh[];

    const int tid  = threadIdx.x;
    const int wid  = tid >> 5;
    const int lane = tid & 31;
    const int g    = lane >> 2;
    const int t    = lane & 3;
    const int q0   = blockIdx.x * 64;
    const int bh   = blockIdx.y;
    const int wq   = wid * 16;

    const __half* Qg = g_qkvh[0] + (size_t)bh * SS * HDD;   // [s][hd] (pre-scaled)
    const __half* Kg = g_qkvh[1] + (size_t)bh * SS * HDD;   // [s][hd]
    const __half* Vg = g_qkvh[2] + (size_t)bh * HDD * SS;   // [hd][s]

    const uint32_t smem_u32 = (uint32_t)__cvta_generic_to_shared(smh);

    const uint32_t lmA =
        (uint32_t)((lane & 7) + ((lane >> 3) & 1) * 8) * RB + ((lane >> 4) & 1) * 16;
    const uint32_t lmB =
        (uint32_t)((lane & 7) + ((lane >> 4) & 1) * 8) * RB + ((lane >> 3) & 1) * 16;

    // ---- prologue: async-fetch tile 0 into stage 0 ----
    #pragma unroll
    for (int c = 0; c < 4; c++) {
        const int chunk = tid + c * 128;   // 0..511
        const int row = chunk >> 3;        // 0..63
        const int qb  = chunk & 7;
        cp16(smem_u32 + (uint32_t)row * RB + qb * 16,
             Kg + (size_t)row * HDD + qb * 8);
        cp16(smem_u32 + STG_B + (uint32_t)row * RB + qb * 16,
             Vg + (size_t)row * SS + qb * 8);
    }
    asm volatile("cp.async.commit_group;\n" ::: "memory");

    // ---- stage Q through stage-1 K region, pull A-fragments ----
    {
        char* smQ = reinterpret_cast<char*>(smh) + STAGE_B;
        #pragma unroll
        for (int c = 0; c < 4; c++) {
            const int chunk = tid + c * 128;
            const int row = chunk >> 3;
            const int qb  = chunk & 7;
            uint4 v = *reinterpret_cast<const uint4*>(
                Qg + (size_t)(q0 + row) * HDD + qb * 8);
            *reinterpret_cast<uint4*>(smQ + (size_t)row * RB + qb * 16) = v;
        }
    }
    __syncthreads();
    uint32_t qf[4][4];
    {
        const uint32_t Qb = smem_u32 + STAGE_B + (uint32_t)wq * RB + lmA;
        #pragma unroll
        for (int ks = 0; ks < 4; ks++)
            ldsm4(qf[ks][0], qf[ks][1], qf[ks][2], qf[ks][3], Qb + ks * 32);
    }

    float o[8][4];
    float l_st0 = 0.0f, l_st1 = 0.0f;
    #pragma unroll
    for (int nt = 0; nt < 8; nt++)
        #pragma unroll
        for (int i = 0; i < 4; i++) o[nt][i] = 0.0f;

    for (int T = 0; T < NT; T++) {
        asm volatile("cp.async.wait_group 0;\n" ::: "memory");
        __syncthreads();

        const int st = T & 1;
        const uint32_t Kb = smem_u32 + (uint32_t)(st * STAGE_B) + lmB;
        const uint32_t Vb = Kb + STG_B;

        if (T + 1 < NT) {
            const int kt1 = (T + 1) * 64;
            const uint32_t sb = smem_u32 + (uint32_t)((st ^ 1) * STAGE_B);
            #pragma unroll
            for (int c = 0; c < 4; c++) {
                const int chunk = tid + c * 128;
                const int row = chunk >> 3;
                const int qb  = chunk & 7;
                cp16(sb + (uint32_t)row * RB + qb * 16,
                     Kg + (size_t)(kt1 + row) * HDD + qb * 8);
                cp16(sb + STG_B + (uint32_t)row * RB + qb * 16,
                     Vg + (size_t)row * SS + kt1 + qb * 8);
            }
            asm volatile("cp.async.commit_group;\n" ::: "memory");
        }

        // scores S = Q @ K^T (log2-scaled); 4 k16 steps over hd
        float s[8][4];
        #pragma unroll
        for (int nt = 0; nt < 8; nt++)
            #pragma unroll
            for (int i = 0; i < 4; i++) s[nt][i] = 0.0f;

        #pragma unroll
        for (int ks = 0; ks < 4; ks++) {
            const uint32_t koff = ks * 32;
            uint32_t b[8][2];
            #pragma unroll
            for (int j = 0; j < 4; j++)
                ldsm4(b[2*j][0], b[2*j][1], b[2*j+1][0], b[2*j+1][1],
                      Kb + (uint32_t)(j * 16) * RB + koff);
            #pragma unroll
            for (int nt = 0; nt < 8; nt++)
                mma_f16(s[nt], qf[ks][0], qf[ks][1], qf[ks][2], qf[ks][3],
                        b[nt][0], b[nt][1]);
        }

        // no-max softmax with fixed shift: p = 2^(s - SHIFT)
        #pragma unroll
        for (int nt = 0; nt < 8; nt++) {
            s[nt][0] = ex2f(s[nt][0] - SHIFT);
            s[nt][1] = ex2f(s[nt][1] - SHIFT);
            s[nt][2] = ex2f(s[nt][2] - SHIFT);
            s[nt][3] = ex2f(s[nt][3] - SHIFT);
            l_st0 += s[nt][0] + s[nt][1];
            l_st1 += s[nt][2] + s[nt][3];
        }

        // O += P @ V : A from lane-local f16x2 packs; V via ldmatrix ([hd][key])
        #pragma unroll
        for (int kt = 0; kt < 4; kt++) {
            const uint32_t a0 = pack_f16(s[2*kt    ][1], s[2*kt    ][0]);
            const uint32_t a1 = pack_f16(s[2*kt    ][3], s[2*kt    ][2]);
            const uint32_t a2 = pack_f16(s[2*kt + 1][1], s[2*kt + 1][0]);
            const uint32_t a3 = pack_f16(s[2*kt + 1][3], s[2*kt + 1][2]);

            const uint32_t koff = kt * 32;    // 16 keys
            uint32_t b[8][2];
            #pragma unroll
            for (int j = 0; j < 4; j++)
                ldsm4(b[2*j][0], b[2*j][1], b[2*j+1][0], b[2*j+1][1],
                      Vb + (uint32_t)(j * 16) * RB + koff);
            #pragma unroll
            for (int nt = 0; nt < 8; nt++)
                mma_f16(o[nt], a0, a1, a2, a3, b[nt][0], b[nt][1]);
        }
    }

    // epilogue: quad-reduce l, normalize, merge heads
    l_st0 += __shfl_xor_sync(0xffffffffu, l_st0, 1);
    l_st0 += __shfl_xor_sync(0xffffffffu, l_st0, 2);
    l_st1 += __shfl_xor_sync(0xffffffffu, l_st1, 1);
    l_st1 += __shfl_xor_sync(0xffffffffu, l_st1, 2);

    const int b_ = bh >> 4;
    const int h  = bh & 15;
    {
        const float inv0 = 1.0f / l_st0;
        const float inv1 = 1.0f / l_st1;
        const int s0 = q0 + wq + g;
        const int s1 = s0 + 8;
        #pragma unroll
        for (int nt = 0; nt < 8; nt++) {
            const int col = h * HDD + nt * 8 + 2 * t;
            float2 v0 = make_float2(o[nt][0] * inv0, o[nt][1] * inv0);
            float2 v1 = make_float2(o[nt][2] * inv1, o[nt][3] * inv1);
            *reinterpret_cast<float2*>(&out[((size_t)b_ * SS + s0) * DDIM + col]) = v0;
            *reinterpret_cast<float2*>(&out[((size_t)b_ * SS + s1) * DDIM + col]) = v1;
        }
    }
}

// ---------------------------------------------------------------------------
// Launch
// ---------------------------------------------------------------------------
extern "C" void kernel_launch(void* const* d_in, const int* in_sizes, int n_in,
                              void* d_out, int out_size)
{
    (void)in_sizes; (void)n_in; (void)out_size;
    const float* q  = (const float*)d_in[0];
    const float* k  = (const float*)d_in[1];
    const float* v  = (const float*)d_in[2];
    const float* Wq = (const float*)d_in[3];
    const float* bq = (const float*)d_in[4];
    const float* Wk = (const float*)d_in[5];
    const float* bk = (const float*)d_in[6];
    const float* Wv = (const float*)d_in[7];
    const float* bv = (const float*)d_in[8];
    float* out = (float*)d_out;

    // Pre-pass: fp16 activations + transposed/scaled fp16 weights
    prep_x_kernel<<<dim3(4096, 3), 256>>>(q, k, v);
    prep_w_kernel<<<dim3(32, 32, 3), dim3(32, 8)>>>(Wq, Wk, Wv);

    // Projection GEMM
    cudaFuncSetAttribute(qkv_proj_kernel,
                         cudaFuncAttributeMaxDynamicSharedMemorySize,
                         QKV_SMEM_BYTES);   // 73,728 B
    qkv_proj_kernel<<<dim3(DDIM / 128, MM / 128, 3), 256, QKV_SMEM_BYTES>>>(bq, bk, bv);

    // Attention
    cudaFuncSetAttribute(attn_kernel,
                         cudaFuncAttributeMaxDynamicSharedMemorySize,
                         ATTN_SMEM_BYTES);  // 36,864 B
    attn_kernel<<<dim3(SS / 64, BB * HH), 128, ATTN_SMEM_BYTES>>>(out);
}